// round 2
// baseline (speedup 1.0000x reference)
#include <cuda_runtime.h>
#include <cuda_bf16.h>
#include <cstddef>

#define N_NODES 100000
#define D 128

// Device scratch (allocation-free rule: __device__ globals)
__device__ __align__(16) float g_sum[(size_t)N_NODES * D];   // 51.2 MB
__device__ __align__(16) float g_deg[N_NODES];
__device__ __align__(16) float g_rdeg[N_NODES];

// ---------------------------------------------------------------------------
// Zero the accumulators (float4 stores, grid-stride)
// ---------------------------------------------------------------------------
__global__ void zero_kernel() {
    size_t i = (size_t)blockIdx.x * blockDim.x + threadIdx.x;
    size_t stride = (size_t)gridDim.x * blockDim.x;
    const size_t n4 = (size_t)N_NODES * D / 4;
    float4 z = make_float4(0.f, 0.f, 0.f, 0.f);
    float4* s4 = reinterpret_cast<float4*>(g_sum);
    for (size_t j = i; j < n4; j += stride) s4[j] = z;
    for (size_t j = i; j < N_NODES; j += stride) g_deg[j] = 0.f;
}

// ---------------------------------------------------------------------------
// Edge aggregation: one warp per edge.
// lane l handles floats [4l, 4l+4): LDG.128 gather + vector float4 atomicAdd
// (sm_90+ native; lowers to RED since the return value is unused).
// ---------------------------------------------------------------------------
__global__ void edge_kernel(const float* __restrict__ feat,
                            const int* __restrict__ src,
                            const int* __restrict__ dst,
                            int E) {
    const int lane  = threadIdx.x & 31;
    const int warp  = (blockIdx.x * blockDim.x + threadIdx.x) >> 5;
    const int nwarp = (gridDim.x * blockDim.x) >> 5;
    for (int e = warp; e < E; e += nwarp) {
        const int s = src[e];
        const int d = dst[e];
        const float4 v = *reinterpret_cast<const float4*>(
            feat + (size_t)s * D + lane * 4);
        atomicAdd(reinterpret_cast<float4*>(g_sum + (size_t)d * D + lane * 4), v);
        if (lane == 0) atomicAdd(&g_deg[d], 1.0f);
    }
}

// ---------------------------------------------------------------------------
// rdeg[i] = 1 / max(deg, 1)
// ---------------------------------------------------------------------------
__global__ void rdeg_kernel() {
    int i = blockIdx.x * blockDim.x + threadIdx.x;
    if (i < N_NODES) g_rdeg[i] = 1.0f / fmaxf(g_deg[i], 1.0f);
}

// ---------------------------------------------------------------------------
// Fused GEMM: out = [feat | g_sum*rdeg] (M x 256) @ [W_self ; W_neigh] (256x128)
//             + (b_self + b_neigh)
// Tiled SGEMM: BM=128, BN=128, BK=16, 256 threads, 8x8 microtile.
// ---------------------------------------------------------------------------
#define BM 128
#define BN 128
#define BK 16

__global__ __launch_bounds__(256) void gemm_kernel(
    const float* __restrict__ feat,
    const float* __restrict__ Wself,
    const float* __restrict__ bself,
    const float* __restrict__ Wneigh,
    const float* __restrict__ bneigh,
    float* __restrict__ out,
    int M) {
    __shared__ float As[BK][BM + 4];   // +4 pad: kill transpose-store conflicts
    __shared__ float Bs[BK][BN];

    const int tid = threadIdx.x;
    const int tx = tid & 15;          // output col group (8 cols)
    const int ty = tid >> 4;          // output row group (8 rows)
    const int blockRow = blockIdx.x * BM;

    float acc[8][8];
#pragma unroll
    for (int i = 0; i < 8; ++i)
#pragma unroll
        for (int j = 0; j < 8; ++j) acc[i][j] = 0.f;

    for (int kc = 0; kc < 256 / BK; ++kc) {
        const int  kbase = kc * BK;
        const bool neigh = (kbase >= 128);
        const int  koff  = neigh ? kbase - 128 : kbase;
        const float* Aglob = neigh ? g_sum : feat;
        const float* Wg    = neigh ? Wneigh : Wself;

        // ---- load A tile (128x16) as float4, store transposed As[k][m] ----
#pragma unroll
        for (int j = 0; j < 2; ++j) {
            const int f  = tid + j * 256;        // float4 id in [0,512)
            const int r  = f >> 2;               // tile row (0..127)
            const int c4 = f & 3;                // float4 within the 16-col chunk
            const int grow = blockRow + r;
            float4 v = make_float4(0.f, 0.f, 0.f, 0.f);
            if (grow < M) {
                v = *reinterpret_cast<const float4*>(
                    Aglob + (size_t)grow * D + koff + c4 * 4);
                if (neigh) {
                    const float sc = g_rdeg[grow];
                    v.x *= sc; v.y *= sc; v.z *= sc; v.w *= sc;
                }
            }
            As[c4 * 4 + 0][r] = v.x;
            As[c4 * 4 + 1][r] = v.y;
            As[c4 * 4 + 2][r] = v.z;
            As[c4 * 4 + 3][r] = v.w;
        }

        // ---- load B tile (16x128) as float4, natural layout ----
#pragma unroll
        for (int j = 0; j < 2; ++j) {
            const int f  = tid + j * 256;        // float4 id in [0,512)
            const int kr = f >> 5;               // k row (0..15)
            const int c4 = f & 31;               // float4 col (0..31)
            const float4 v = *reinterpret_cast<const float4*>(
                Wg + (size_t)(koff + kr) * 128 + c4 * 4);
            *reinterpret_cast<float4*>(&Bs[kr][c4 * 4]) = v;
        }
        __syncthreads();

        // ---- compute ----
#pragma unroll
        for (int k = 0; k < BK; ++k) {
            float ra[8], rb[8];
#pragma unroll
            for (int i = 0; i < 8; ++i) ra[i] = As[k][ty * 8 + i];
#pragma unroll
            for (int j = 0; j < 8; ++j) rb[j] = Bs[k][tx * 8 + j];
#pragma unroll
            for (int i = 0; i < 8; ++i)
#pragma unroll
                for (int j = 0; j < 8; ++j)
                    acc[i][j] += ra[i] * rb[j];
        }
        __syncthreads();
    }

    // ---- epilogue: add fused bias, guarded store ----
#pragma unroll
    for (int j = 0; j < 8; ++j) {
        const int col = tx * 8 + j;
        const float bias = bself[col] + bneigh[col];
#pragma unroll
        for (int i = 0; i < 8; ++i) {
            const int row = blockRow + ty * 8 + i;
            if (row < M) out[(size_t)row * D + col] = acc[i][j] + bias;
        }
    }
}

// ---------------------------------------------------------------------------
extern "C" void kernel_launch(void* const* d_in, const int* in_sizes, int n_in,
                              void* d_out, int out_size) {
    const float* feat   = (const float*)d_in[0];
    const int*   src    = (const int*)d_in[1];
    const int*   dst    = (const int*)d_in[2];
    const float* Wself  = (const float*)d_in[3];
    const float* bself  = (const float*)d_in[4];
    const float* Wneigh = (const float*)d_in[5];
    const float* bneigh = (const float*)d_in[6];
    float*       out    = (float*)d_out;

    const int E = in_sizes[1];
    const int M = in_sizes[0] / D;

    zero_kernel<<<2048, 256>>>();
    edge_kernel<<<148 * 16, 256>>>(feat, src, dst, E);
    rdeg_kernel<<<(N_NODES + 255) / 256, 256>>>();
    gemm_kernel<<<(M + BM - 1) / BM, 256>>>(feat, Wself, bself, Wneigh, bneigh,
                                            out, M);
}

// round 3
// speedup vs baseline: 1.4145x; 1.4145x over previous
#include <cuda_runtime.h>
#include <cuda_bf16.h>
#include <cstddef>

#define N_NODES 100000
#define D 128
#define E_CAP 3400000

// ---- device scratch (allocation-free rule: __device__ globals) ----
__device__ __align__(16) float g_hn[(size_t)N_NODES * D];   // h_neigh, 51.2 MB
__device__ __align__(16) int   g_count[N_NODES];
__device__ __align__(16) int   g_off[N_NODES];
__device__ __align__(16) int   g_cursor[N_NODES];
__device__ __align__(16) float g_rdeg[N_NODES];
__device__ __align__(16) int   g_csr[E_CAP];                // src sorted by dst
__device__ int g_blocksums[128];

// ---------------------------------------------------------------------------
// 1. zero in-degree counters
// ---------------------------------------------------------------------------
__global__ void zero_cnt_kernel() {
    int i = blockIdx.x * blockDim.x + threadIdx.x;
    if (i < N_NODES) g_count[i] = 0;
}

// ---------------------------------------------------------------------------
// 2. histogram: in-degree per dst
// ---------------------------------------------------------------------------
__global__ void hist_kernel(const int* __restrict__ dst, int E) {
    int i = blockIdx.x * blockDim.x + threadIdx.x;
    int stride = gridDim.x * blockDim.x;
    for (int e = i; e < E; e += stride) atomicAdd(&g_count[dst[e]], 1);
}

// ---------------------------------------------------------------------------
// 3a. per-block exclusive scan (1024 elems/block)
// ---------------------------------------------------------------------------
__global__ __launch_bounds__(1024) void scan_block_kernel() {
    __shared__ int s[1024];
    const int tid = threadIdx.x;
    const int gid = blockIdx.x * 1024 + tid;
    const int v = (gid < N_NODES) ? g_count[gid] : 0;
    s[tid] = v;
    __syncthreads();
#pragma unroll
    for (int o = 1; o < 1024; o <<= 1) {
        int t = 0;
        if (tid >= o) t = s[tid - o];
        __syncthreads();
        if (tid >= o) s[tid] += t;
        __syncthreads();
    }
    if (gid < N_NODES) g_off[gid] = s[tid] - v;   // exclusive
    if (tid == 1023) g_blocksums[blockIdx.x] = s[1023];
}

// 3b. scan the 98 block sums (serial, trivial size)
__global__ void scan_sums_kernel(int nblocks) {
    if (threadIdx.x == 0 && blockIdx.x == 0) {
        int run = 0;
        for (int i = 0; i < nblocks; ++i) {
            int t = g_blocksums[i];
            g_blocksums[i] = run;
            run += t;
        }
    }
}

// 3c. add block offsets, init cursor, compute rdeg
__global__ void scan_fixup_kernel() {
    int i = blockIdx.x * blockDim.x + threadIdx.x;
    if (i < N_NODES) {
        int o = g_off[i] + g_blocksums[i >> 10];
        g_off[i] = o;
        g_cursor[i] = o;
        g_rdeg[i] = 1.0f / fmaxf((float)g_count[i], 1.0f);
    }
}

// ---------------------------------------------------------------------------
// 4. scatter: bucket src ids by dst
// ---------------------------------------------------------------------------
__global__ void scatter_kernel(const int* __restrict__ src,
                               const int* __restrict__ dst, int E) {
    int i = blockIdx.x * blockDim.x + threadIdx.x;
    int stride = gridDim.x * blockDim.x;
    for (int e = i; e < E; e += stride) {
        int pos = atomicAdd(&g_cursor[dst[e]], 1);
        g_csr[pos] = src[e];
    }
}

// ---------------------------------------------------------------------------
// 5. aggregate: one warp per node, register accumulation, single write
// ---------------------------------------------------------------------------
__global__ __launch_bounds__(256) void agg_kernel(const float* __restrict__ feat) {
    const int lane = threadIdx.x & 31;
    const int node = (blockIdx.x * blockDim.x + threadIdx.x) >> 5;
    if (node >= N_NODES) return;

    const int off = g_off[node];
    const int cnt = g_count[node];

    float4 acc = make_float4(0.f, 0.f, 0.f, 0.f);
    int t = 0;
    // unrolled-by-4 main chunks: 4 independent gathers in flight
    for (; t + 4 <= cnt; t += 4) {
        int s0 = g_csr[off + t + 0];
        int s1 = g_csr[off + t + 1];
        int s2 = g_csr[off + t + 2];
        int s3 = g_csr[off + t + 3];
        float4 v0 = *reinterpret_cast<const float4*>(feat + (size_t)s0 * D + lane * 4);
        float4 v1 = *reinterpret_cast<const float4*>(feat + (size_t)s1 * D + lane * 4);
        float4 v2 = *reinterpret_cast<const float4*>(feat + (size_t)s2 * D + lane * 4);
        float4 v3 = *reinterpret_cast<const float4*>(feat + (size_t)s3 * D + lane * 4);
        acc.x += v0.x + v1.x; acc.y += v0.y + v1.y;
        acc.z += v0.z + v1.z; acc.w += v0.w + v1.w;
        acc.x += v2.x + v3.x; acc.y += v2.y + v3.y;
        acc.z += v2.z + v3.z; acc.w += v2.w + v3.w;
    }
    for (; t < cnt; ++t) {
        int s = g_csr[off + t];
        float4 v = *reinterpret_cast<const float4*>(feat + (size_t)s * D + lane * 4);
        acc.x += v.x; acc.y += v.y; acc.z += v.z; acc.w += v.w;
    }
    const float r = g_rdeg[node];
    acc.x *= r; acc.y *= r; acc.z *= r; acc.w *= r;
    *reinterpret_cast<float4*>(g_hn + (size_t)node * D + lane * 4) = acc;
}

// ---------------------------------------------------------------------------
// 6. Fused GEMM: out = [feat | h_neigh] (M x 256) @ [W_self ; W_neigh] (256x128)
//                + (b_self + b_neigh)
//    Double-buffered smem, register prefetch, vector LDS operands.
// ---------------------------------------------------------------------------
#define BM 128
#define BN 128
#define BK 16

__global__ __launch_bounds__(256, 2) void gemm_kernel(
    const float* __restrict__ feat,
    const float* __restrict__ Wself,
    const float* __restrict__ bself,
    const float* __restrict__ Wneigh,
    const float* __restrict__ bneigh,
    float* __restrict__ out,
    int M) {
    __shared__ float As[2][BK][BM + 4];
    __shared__ float Bs[2][BK][BN];

    const int tid = threadIdx.x;
    const int tx = tid & 15;
    const int ty = tid >> 4;
    const int blockRow = blockIdx.x * BM;

    // A-load indexing (fixed per thread): 512 float4s, 2 per thread
    const int ar0 = (tid + 0) >> 2,   ac0 = (tid + 0) & 3;
    const int ar1 = (tid + 256) >> 2, ac1 = (tid + 256) & 3;
    // B-load indexing
    const int bk0 = (tid + 0) >> 5,   bc0 = (tid + 0) & 31;
    const int bk1 = (tid + 256) >> 5, bc1 = (tid + 256) & 31;

    float4 a_reg[2], b_reg[2];

    auto load_chunk = [&](int kc) {
        const int  kbase = kc * BK;
        const bool neigh = (kbase >= 128);
        const int  koff  = kbase & 127;
        const float* Ag = neigh ? g_hn : feat;
        const float* Wg = neigh ? Wneigh : Wself;

        int grow0 = blockRow + ar0;
        int grow1 = blockRow + ar1;
        a_reg[0] = (grow0 < M)
            ? *reinterpret_cast<const float4*>(Ag + (size_t)grow0 * D + koff + ac0 * 4)
            : make_float4(0.f, 0.f, 0.f, 0.f);
        a_reg[1] = (grow1 < M)
            ? *reinterpret_cast<const float4*>(Ag + (size_t)grow1 * D + koff + ac1 * 4)
            : make_float4(0.f, 0.f, 0.f, 0.f);
        b_reg[0] = *reinterpret_cast<const float4*>(Wg + (size_t)(koff + bk0) * 128 + bc0 * 4);
        b_reg[1] = *reinterpret_cast<const float4*>(Wg + (size_t)(koff + bk1) * 128 + bc1 * 4);
    };

    auto store_chunk = [&](int buf) {
        As[buf][ac0 * 4 + 0][ar0] = a_reg[0].x;
        As[buf][ac0 * 4 + 1][ar0] = a_reg[0].y;
        As[buf][ac0 * 4 + 2][ar0] = a_reg[0].z;
        As[buf][ac0 * 4 + 3][ar0] = a_reg[0].w;
        As[buf][ac1 * 4 + 0][ar1] = a_reg[1].x;
        As[buf][ac1 * 4 + 1][ar1] = a_reg[1].y;
        As[buf][ac1 * 4 + 2][ar1] = a_reg[1].z;
        As[buf][ac1 * 4 + 3][ar1] = a_reg[1].w;
        *reinterpret_cast<float4*>(&Bs[buf][bk0][bc0 * 4]) = b_reg[0];
        *reinterpret_cast<float4*>(&Bs[buf][bk1][bc1 * 4]) = b_reg[1];
    };

    float acc[8][8];
#pragma unroll
    for (int i = 0; i < 8; ++i)
#pragma unroll
        for (int j = 0; j < 8; ++j) acc[i][j] = 0.f;

    load_chunk(0);
    store_chunk(0);
    __syncthreads();

    const int NKC = 256 / BK;  // 16
#pragma unroll 1
    for (int kc = 0; kc < NKC; ++kc) {
        const int buf = kc & 1;
        if (kc + 1 < NKC) load_chunk(kc + 1);

#pragma unroll
        for (int k = 0; k < BK; ++k) {
            float4 a0 = *reinterpret_cast<const float4*>(&As[buf][k][ty * 8]);
            float4 a1 = *reinterpret_cast<const float4*>(&As[buf][k][ty * 8 + 4]);
            float4 b0 = *reinterpret_cast<const float4*>(&Bs[buf][k][tx * 8]);
            float4 b1 = *reinterpret_cast<const float4*>(&Bs[buf][k][tx * 8 + 4]);
            const float ra[8] = {a0.x, a0.y, a0.z, a0.w, a1.x, a1.y, a1.z, a1.w};
            const float rb[8] = {b0.x, b0.y, b0.z, b0.w, b1.x, b1.y, b1.z, b1.w};
#pragma unroll
            for (int i = 0; i < 8; ++i)
#pragma unroll
                for (int j = 0; j < 8; ++j)
                    acc[i][j] += ra[i] * rb[j];
        }

        if (kc + 1 < NKC) {
            store_chunk(buf ^ 1);
            __syncthreads();
        }
    }

    // epilogue
#pragma unroll
    for (int j = 0; j < 8; ++j) {
        const int col = tx * 8 + j;
        const float bias = bself[col] + bneigh[col];
#pragma unroll
        for (int i = 0; i < 8; ++i) {
            const int row = blockRow + ty * 8 + i;
            if (row < M) out[(size_t)row * D + col] = acc[i][j] + bias;
        }
    }
}

// ---------------------------------------------------------------------------
extern "C" void kernel_launch(void* const* d_in, const int* in_sizes, int n_in,
                              void* d_out, int out_size) {
    const float* feat   = (const float*)d_in[0];
    const int*   src    = (const int*)d_in[1];
    const int*   dst    = (const int*)d_in[2];
    const float* Wself  = (const float*)d_in[3];
    const float* bself  = (const float*)d_in[4];
    const float* Wneigh = (const float*)d_in[5];
    const float* bneigh = (const float*)d_in[6];
    float*       out    = (float*)d_out;

    const int E = in_sizes[1];
    const int M = in_sizes[0] / D;
    const int nScanBlocks = (N_NODES + 1023) / 1024;   // 98

    zero_cnt_kernel<<<(N_NODES + 255) / 256, 256>>>();
    hist_kernel<<<148 * 16, 256>>>(dst, E);
    scan_block_kernel<<<nScanBlocks, 1024>>>();
    scan_sums_kernel<<<1, 32>>>(nScanBlocks);
    scan_fixup_kernel<<<(N_NODES + 255) / 256, 256>>>();
    scatter_kernel<<<148 * 16, 256>>>(src, dst, E);
    agg_kernel<<<(N_NODES * 32 + 255) / 256, 256>>>(feat);
    gemm_kernel<<<(M + BM - 1) / BM, 256>>>(feat, Wself, bself, Wneigh, bneigh,
                                            out, M);
}

// round 5
// speedup vs baseline: 2.4265x; 1.7154x over previous
#include <cuda_runtime.h>
#include <cuda_bf16.h>
#include <cstdint>
#include <cstddef>

#define N_NODES 100000
#define D 128
#define E_CAP 3400000

// ---- device scratch (allocation-free rule: __device__ globals) ----
__device__ __align__(16) float g_hn[(size_t)N_NODES * D];   // h_neigh, 51.2 MB
__device__ __align__(16) int   g_count[N_NODES];
__device__ __align__(16) int   g_off[N_NODES];
__device__ __align__(16) int   g_cursor[N_NODES];
__device__ __align__(16) float g_rdeg[N_NODES];
__device__ __align__(16) int   g_csr[E_CAP];
__device__ int g_blocksums[128];
// W transposed to [half][n][k], tf32-rounded fp32 bits
__device__ __align__(16) float g_W[2][128 * 256];
__device__ __align__(16) float g_bias[D];

// ===========================================================================
// tf32 helpers (base PTX, sm_80+; no arch-specific features)
// ===========================================================================
__device__ __forceinline__ uint32_t to_tf32(float f) {
    uint32_t r;
    asm("cvt.rna.tf32.f32 %0, %1;" : "=r"(r) : "f"(f));
    return r;
}

__device__ __forceinline__ void mma_tf32(float& c0, float& c1, float& c2, float& c3,
                                         uint32_t a0, uint32_t a1, uint32_t a2, uint32_t a3,
                                         uint32_t b0, uint32_t b1) {
    asm volatile(
        "mma.sync.aligned.m16n8k8.row.col.f32.tf32.tf32.f32 "
        "{%0,%1,%2,%3}, {%4,%5,%6,%7}, {%8,%9}, {%0,%1,%2,%3};"
        : "+f"(c0), "+f"(c1), "+f"(c2), "+f"(c3)
        : "r"(a0), "r"(a1), "r"(a2), "r"(a3), "r"(b0), "r"(b1));
}

// ===========================================================================
// CSR build
// ===========================================================================
__global__ void zero_cnt_kernel() {
    int i = blockIdx.x * blockDim.x + threadIdx.x;
    if (i < N_NODES) g_count[i] = 0;
}

__global__ void hist_kernel(const int* __restrict__ dst, int E) {
    int i = blockIdx.x * blockDim.x + threadIdx.x;
    int stride = gridDim.x * blockDim.x;
    for (int e = i; e < E; e += stride) atomicAdd(&g_count[dst[e]], 1);
}

__global__ __launch_bounds__(1024) void scan_block_kernel() {
    __shared__ int s[1024];
    const int tid = threadIdx.x;
    const int gid = blockIdx.x * 1024 + tid;
    const int v = (gid < N_NODES) ? g_count[gid] : 0;
    s[tid] = v;
    __syncthreads();
#pragma unroll
    for (int o = 1; o < 1024; o <<= 1) {
        int t = 0;
        if (tid >= o) t = s[tid - o];
        __syncthreads();
        if (tid >= o) s[tid] += t;
        __syncthreads();
    }
    if (gid < N_NODES) g_off[gid] = s[tid] - v;
    if (tid == 1023) g_blocksums[blockIdx.x] = s[1023];
}

// parallel scan of the (<=128) block sums
__global__ void scan_sums_kernel(int n) {
    __shared__ int s[128];
    const int tid = threadIdx.x;
    const int v = (tid < n) ? g_blocksums[tid] : 0;
    s[tid] = v;
    __syncthreads();
#pragma unroll
    for (int o = 1; o < 128; o <<= 1) {
        int t = 0;
        if (tid >= o) t = s[tid - o];
        __syncthreads();
        if (tid >= o) s[tid] += t;
        __syncthreads();
    }
    if (tid < n) g_blocksums[tid] = s[tid] - v;   // exclusive
}

__global__ void scan_fixup_kernel() {
    int i = blockIdx.x * blockDim.x + threadIdx.x;
    if (i < N_NODES) {
        int o = g_off[i] + g_blocksums[i >> 10];
        g_off[i] = o;
        g_cursor[i] = o;
        g_rdeg[i] = 1.0f / fmaxf((float)g_count[i], 1.0f);
    }
}

__global__ void scatter_kernel(const int* __restrict__ src,
                               const int* __restrict__ dst, int E) {
    int i = blockIdx.x * blockDim.x + threadIdx.x;
    int stride = gridDim.x * blockDim.x;
    for (int e = i; e < E; e += stride) {
        int pos = atomicAdd(&g_cursor[dst[e]], 1);
        g_csr[pos] = src[e];
    }
}

// ===========================================================================
// aggregate: one warp per node
// ===========================================================================
__global__ __launch_bounds__(256) void agg_kernel(const float* __restrict__ feat) {
    const int lane = threadIdx.x & 31;
    const int node = (blockIdx.x * blockDim.x + threadIdx.x) >> 5;
    if (node >= N_NODES) return;

    const int off = g_off[node];
    const int cnt = g_count[node];

    float4 acc = make_float4(0.f, 0.f, 0.f, 0.f);
    int t = 0;
    for (; t + 4 <= cnt; t += 4) {
        int s0 = g_csr[off + t + 0];
        int s1 = g_csr[off + t + 1];
        int s2 = g_csr[off + t + 2];
        int s3 = g_csr[off + t + 3];
        float4 v0 = *reinterpret_cast<const float4*>(feat + (size_t)s0 * D + lane * 4);
        float4 v1 = *reinterpret_cast<const float4*>(feat + (size_t)s1 * D + lane * 4);
        float4 v2 = *reinterpret_cast<const float4*>(feat + (size_t)s2 * D + lane * 4);
        float4 v3 = *reinterpret_cast<const float4*>(feat + (size_t)s3 * D + lane * 4);
        acc.x += v0.x + v1.x; acc.y += v0.y + v1.y;
        acc.z += v0.z + v1.z; acc.w += v0.w + v1.w;
        acc.x += v2.x + v3.x; acc.y += v2.y + v3.y;
        acc.z += v2.z + v3.z; acc.w += v2.w + v3.w;
    }
    for (; t < cnt; ++t) {
        int s = g_csr[off + t];
        float4 v = *reinterpret_cast<const float4*>(feat + (size_t)s * D + lane * 4);
        acc.x += v.x; acc.y += v.y; acc.z += v.z; acc.w += v.w;
    }
    const float r = g_rdeg[node];
    acc.x *= r; acc.y *= r; acc.z *= r; acc.w *= r;
    *reinterpret_cast<float4*>(g_hn + (size_t)node * D + lane * 4) = acc;
}

// ===========================================================================
// prep: W -> transposed [n][k], tf32-rounded; fused bias
// ===========================================================================
__global__ void prep_w_kernel(const float* __restrict__ Wself,
                              const float* __restrict__ Wneigh,
                              const float* __restrict__ bself,
                              const float* __restrict__ bneigh) {
    int idx = blockIdx.x * blockDim.x + threadIdx.x;   // 0..65535
    if (idx < 128) g_bias[idx] = bself[idx] + bneigh[idx];
    if (idx >= 2 * 128 * 256) return;
    const int h = idx >> 15;
    const int n = (idx >> 8) & 127;
    const int k = idx & 255;
    const float* W = (k < 128) ? (h ? Wneigh : Wself) : nullptr;
    float w = 0.f;
    if (k < 128) w = W[k * 128 + n];                   // B[n][k] = W[k][n]
    // layout [h][n][256]: k in [0,128) real, [128,256) unused (keep simple: 256-k image
    // actually K per half is 128; store only k<128 region, padded image width 256 unused)
    uint32_t t = to_tf32(w);
    g_W[h][n * 256 + k] = __uint_as_float(t);
}

// ===========================================================================
// GEMM: out = [feat | g_hn] (M x 256) @ [Wself ; Wneigh]^T-images + bias
// tf32 mma.sync m16n8k8 (single pass, RNE-rounded operands).
// CTA 128x128, 8 warps of 64x32, K chunked at 64.
// smem: As[128][68] + Bs[128][68] floats = 69.6 KB (dynamic).
// ===========================================================================
#define ASTRIDE 68

__global__ __launch_bounds__(256, 2) void gemm_kernel(
    const float* __restrict__ feat,
    float* __restrict__ out,
    int M) {
    extern __shared__ float smem[];
    float* As = smem;                      // [128][ASTRIDE]
    float* Bs = smem + 128 * ASTRIDE;      // [128][ASTRIDE]

    const int tid  = threadIdx.x;
    const int wid  = tid >> 5;
    const int lane = tid & 31;
    const int blockRow = blockIdx.x * 128;

    const int wm = wid >> 2;               // 0..1  -> rows wm*64
    const int wn = wid & 3;                // 0..3  -> cols wn*32
    const int qr = lane >> 2;              // 0..7
    const int qc = lane & 3;               // 0..3

    float acc[4][4][4];
#pragma unroll
    for (int mt = 0; mt < 4; ++mt)
#pragma unroll
        for (int nt = 0; nt < 4; ++nt)
#pragma unroll
            for (int j = 0; j < 4; ++j) acc[mt][nt][j] = 0.f;

#pragma unroll 1
    for (int it = 0; it < 4; ++it) {
        const int h     = it >> 1;
        const int cbase = (it & 1) * 64;
        const float* Ag = h ? g_hn : feat;

        if (it) __syncthreads();           // previous compute done

        // ---- A tile: 128x64 fp32 -> tf32-rounded smem ----
#pragma unroll
        for (int j = 0; j < 8; ++j) {
            const int g   = j * 256 + tid;     // 0..2047 float4 slots
            const int row = g >> 4;
            const int c4  = (g & 15) * 4;
            const int grow = blockRow + row;
            float4 v = make_float4(0.f, 0.f, 0.f, 0.f);
            if (grow < M)
                v = *reinterpret_cast<const float4*>(
                    Ag + (size_t)grow * D + cbase + c4);
            float* dstp = As + row * ASTRIDE + c4;
            dstp[0] = __uint_as_float(to_tf32(v.x));
            dstp[1] = __uint_as_float(to_tf32(v.y));
            dstp[2] = __uint_as_float(to_tf32(v.z));
            dstp[3] = __uint_as_float(to_tf32(v.w));
        }
        // ---- B tile: copy pre-rounded [n][k-chunk] ----
#pragma unroll
        for (int j = 0; j < 8; ++j) {
            const int g   = j * 256 + tid;
            const int row = g >> 4;
            const int c4  = (g & 15) * 4;
            const float4 v = *reinterpret_cast<const float4*>(
                g_W[h] + (size_t)row * 256 + cbase + c4);
            *reinterpret_cast<float4*>(Bs + row * ASTRIDE + c4) = v;
        }
        __syncthreads();

        // ---- compute: 8 k8-steps ----
#pragma unroll
        for (int ks = 0; ks < 8; ++ks) {
            const int kb = ks * 8;
            uint32_t a[4][4], b[4][2];
#pragma unroll
            for (int mt = 0; mt < 4; ++mt) {
                const int rb = wm * 64 + mt * 16;
                const uint32_t* ap =
                    reinterpret_cast<const uint32_t*>(As + (rb + qr) * ASTRIDE + kb + qc);
                a[mt][0] = ap[0];
                a[mt][2] = ap[4];
                const uint32_t* ap8 =
                    reinterpret_cast<const uint32_t*>(As + (rb + qr + 8) * ASTRIDE + kb + qc);
                a[mt][1] = ap8[0];
                a[mt][3] = ap8[4];
            }
#pragma unroll
            for (int nt = 0; nt < 4; ++nt) {
                const int nb = wn * 32 + nt * 8;
                const uint32_t* bp =
                    reinterpret_cast<const uint32_t*>(Bs + (nb + qr) * ASTRIDE + kb + qc);
                b[nt][0] = bp[0];
                b[nt][1] = bp[4];
            }
#pragma unroll
            for (int mt = 0; mt < 4; ++mt)
#pragma unroll
                for (int nt = 0; nt < 4; ++nt)
                    mma_tf32(acc[mt][nt][0], acc[mt][nt][1],
                             acc[mt][nt][2], acc[mt][nt][3],
                             a[mt][0], a[mt][1], a[mt][2], a[mt][3],
                             b[nt][0], b[nt][1]);
        }
    }

    // ---- epilogue: direct register -> global stores with fused bias ----
#pragma unroll
    for (int mt = 0; mt < 4; ++mt) {
        const int r0 = blockRow + wm * 64 + mt * 16 + qr;
#pragma unroll
        for (int nt = 0; nt < 4; ++nt) {
            const int col = wn * 32 + nt * 8 + qc * 2;
            const float b0 = g_bias[col];
            const float b1 = g_bias[col + 1];
            if (r0 < M) {
                float2 o = make_float2(acc[mt][nt][0] + b0, acc[mt][nt][1] + b1);
                *reinterpret_cast<float2*>(out + (size_t)r0 * D + col) = o;
            }
            if (r0 + 8 < M) {
                float2 o = make_float2(acc[mt][nt][2] + b0, acc[mt][nt][3] + b1);
                *reinterpret_cast<float2*>(out + (size_t)(r0 + 8) * D + col) = o;
            }
        }
    }
}

// ---------------------------------------------------------------------------
extern "C" void kernel_launch(void* const* d_in, const int* in_sizes, int n_in,
                              void* d_out, int out_size) {
    const float* feat   = (const float*)d_in[0];
    const int*   src    = (const int*)d_in[1];
    const int*   dst    = (const int*)d_in[2];
    const float* Wself  = (const float*)d_in[3];
    const float* bself  = (const float*)d_in[4];
    const float* Wneigh = (const float*)d_in[5];
    const float* bneigh = (const float*)d_in[6];
    float*       out    = (float*)d_out;

    const int E = in_sizes[1];
    const int M = in_sizes[0] / D;
    const int nScanBlocks = (N_NODES + 1023) / 1024;   // 98
    const int GEMM_SMEM = 2 * 128 * ASTRIDE * 4;       // 69632 B

    cudaFuncSetAttribute(gemm_kernel, cudaFuncAttributeMaxDynamicSharedMemorySize,
                         GEMM_SMEM);

    prep_w_kernel<<<256, 256>>>(Wself, Wneigh, bself, bneigh);
    zero_cnt_kernel<<<(N_NODES + 255) / 256, 256>>>();
    hist_kernel<<<148 * 16, 256>>>(dst, E);
    scan_block_kernel<<<nScanBlocks, 1024>>>();
    scan_sums_kernel<<<1, 128>>>(nScanBlocks);
    scan_fixup_kernel<<<(N_NODES + 255) / 256, 256>>>();
    scatter_kernel<<<148 * 16, 256>>>(src, dst, E);
    agg_kernel<<<(N_NODES * 32 + 255) / 256, 256>>>(feat);
    gemm_kernel<<<(M + 127) / 128, 256, GEMM_SMEM>>>(feat, out, M);
}

// round 6
// speedup vs baseline: 2.5497x; 1.0508x over previous
#include <cuda_runtime.h>
#include <cuda_bf16.h>
#include <cstdint>
#include <cstddef>

#define N_NODES 100000
#define D 128
#define E_CAP 3400000

// ---- device scratch (allocation-free rule: __device__ globals) ----
__device__ __align__(16) float g_hn[(size_t)N_NODES * D];       // h_neigh, 51.2 MB
__device__ __align__(16) __nv_bfloat16 g_featb[(size_t)N_NODES * D];  // 25.6 MB
__device__ __align__(16) int   g_count[N_NODES];
__device__ __align__(16) int   g_off[N_NODES];
__device__ __align__(16) int   g_cursor[N_NODES];
__device__ __align__(16) float g_rdeg[N_NODES];
__device__ __align__(16) int   g_csr[E_CAP];
__device__ int g_blocksums[128];
// W transposed to [half][n][k-image], tf32-rounded fp32 bits
__device__ __align__(16) float g_W[2][128 * 256];
__device__ __align__(16) float g_bias[D];

// ===========================================================================
// tf32 helpers (base PTX, sm_80+)
// ===========================================================================
__device__ __forceinline__ uint32_t to_tf32(float f) {
    uint32_t r;
    asm("cvt.rna.tf32.f32 %0, %1;" : "=r"(r) : "f"(f));
    return r;
}

__device__ __forceinline__ void mma_tf32(float& c0, float& c1, float& c2, float& c3,
                                         uint32_t a0, uint32_t a1, uint32_t a2, uint32_t a3,
                                         uint32_t b0, uint32_t b1) {
    asm volatile(
        "mma.sync.aligned.m16n8k8.row.col.f32.tf32.tf32.f32 "
        "{%0,%1,%2,%3}, {%4,%5,%6,%7}, {%8,%9}, {%0,%1,%2,%3};"
        : "+f"(c0), "+f"(c1), "+f"(c2), "+f"(c3)
        : "r"(a0), "r"(a1), "r"(a2), "r"(a3), "r"(b0), "r"(b1));
}

// bf16x2 (packed in u32) -> two fp32 via pure bit ops
__device__ __forceinline__ void bf2x_to_f32(uint32_t u, float& lo, float& hi) {
    lo = __uint_as_float(u << 16);
    hi = __uint_as_float(u & 0xFFFF0000u);
}

// ===========================================================================
// prep: W transpose + tf32 round, fused bias, zero counters (one launch)
// ===========================================================================
__global__ void prep_kernel(const float* __restrict__ Wself,
                            const float* __restrict__ Wneigh,
                            const float* __restrict__ bself,
                            const float* __restrict__ bneigh) {
    int idx = blockIdx.x * blockDim.x + threadIdx.x;   // grid covers >= N_NODES
    if (idx < 128) g_bias[idx] = bself[idx] + bneigh[idx];
    if (idx < N_NODES) g_count[idx] = 0;
    if (idx < 2 * 128 * 128) {
        const int h = idx >> 14;
        const int n = (idx >> 7) & 127;
        const int k = idx & 127;
        const float* W = h ? Wneigh : Wself;
        const float w = W[k * 128 + n];                // B[n][k] = W[k][n]
        g_W[h][n * 256 + k] = __uint_as_float(to_tf32(w));
    }
}

// feat (fp32) -> bf16 image
__global__ void feat2bf16_kernel(const float* __restrict__ feat) {
    const size_t n4 = (size_t)N_NODES * D / 4;
    size_t i = (size_t)blockIdx.x * blockDim.x + threadIdx.x;
    size_t stride = (size_t)gridDim.x * blockDim.x;
    for (size_t j = i; j < n4; j += stride) {
        float4 v = reinterpret_cast<const float4*>(feat)[j];
        uint32_t p0 = ((uint32_t)__bfloat16_as_ushort(__float2bfloat16(v.y)) << 16)
                    | (uint32_t)__bfloat16_as_ushort(__float2bfloat16(v.x));
        uint32_t p1 = ((uint32_t)__bfloat16_as_ushort(__float2bfloat16(v.w)) << 16)
                    | (uint32_t)__bfloat16_as_ushort(__float2bfloat16(v.z));
        reinterpret_cast<uint2*>(g_featb)[j] = make_uint2(p0, p1);
    }
}

// ===========================================================================
// CSR build
// ===========================================================================
__global__ void hist_kernel(const int* __restrict__ dst, int E) {
    int i = blockIdx.x * blockDim.x + threadIdx.x;
    int stride = gridDim.x * blockDim.x;
    for (int e = i; e < E; e += stride) atomicAdd(&g_count[dst[e]], 1);
}

__global__ __launch_bounds__(1024) void scan_block_kernel() {
    __shared__ int s[1024];
    const int tid = threadIdx.x;
    const int gid = blockIdx.x * 1024 + tid;
    const int v = (gid < N_NODES) ? g_count[gid] : 0;
    s[tid] = v;
    __syncthreads();
#pragma unroll
    for (int o = 1; o < 1024; o <<= 1) {
        int t = 0;
        if (tid >= o) t = s[tid - o];
        __syncthreads();
        if (tid >= o) s[tid] += t;
        __syncthreads();
    }
    if (gid < N_NODES) g_off[gid] = s[tid] - v;
    if (tid == 1023) g_blocksums[blockIdx.x] = s[1023];
}

__global__ void scan_sums_kernel(int n) {
    __shared__ int s[128];
    const int tid = threadIdx.x;
    const int v = (tid < n) ? g_blocksums[tid] : 0;
    s[tid] = v;
    __syncthreads();
#pragma unroll
    for (int o = 1; o < 128; o <<= 1) {
        int t = 0;
        if (tid >= o) t = s[tid - o];
        __syncthreads();
        if (tid >= o) s[tid] += t;
        __syncthreads();
    }
    if (tid < n) g_blocksums[tid] = s[tid] - v;   // exclusive
}

__global__ void scan_fixup_kernel() {
    int i = blockIdx.x * blockDim.x + threadIdx.x;
    if (i < N_NODES) {
        int o = g_off[i] + g_blocksums[i >> 10];
        g_off[i] = o;
        g_cursor[i] = o;
        g_rdeg[i] = 1.0f / fmaxf((float)g_count[i], 1.0f);
    }
}

__global__ void scatter_kernel(const int* __restrict__ src,
                               const int* __restrict__ dst, int E) {
    int i = blockIdx.x * blockDim.x + threadIdx.x;
    int stride = gridDim.x * blockDim.x;
    for (int e = i; e < E; e += stride) {
        int pos = atomicAdd(&g_cursor[dst[e]], 1);
        g_csr[pos] = src[e];
    }
}

// ===========================================================================
// aggregate: one warp per node, bf16 gathers (8 B/lane), fp32 accumulate
// ===========================================================================
__global__ __launch_bounds__(256) void agg_kernel() {
    const int lane = threadIdx.x & 31;
    const int node = (blockIdx.x * blockDim.x + threadIdx.x) >> 5;
    if (node >= N_NODES) return;

    const int off = g_off[node];
    const int cnt = g_count[node];
    const uint2* fb = reinterpret_cast<const uint2*>(g_featb) + lane;  // +row*32

    float4 acc = make_float4(0.f, 0.f, 0.f, 0.f);
    int t = 0;
    for (; t + 4 <= cnt; t += 4) {
        const int s0 = g_csr[off + t + 0];
        const int s1 = g_csr[off + t + 1];
        const int s2 = g_csr[off + t + 2];
        const int s3 = g_csr[off + t + 3];
        const uint2 u0 = fb[(size_t)s0 * 32];
        const uint2 u1 = fb[(size_t)s1 * 32];
        const uint2 u2 = fb[(size_t)s2 * 32];
        const uint2 u3 = fb[(size_t)s3 * 32];
        float a, b;
        bf2x_to_f32(u0.x, a, b); acc.x += a; acc.y += b;
        bf2x_to_f32(u0.y, a, b); acc.z += a; acc.w += b;
        bf2x_to_f32(u1.x, a, b); acc.x += a; acc.y += b;
        bf2x_to_f32(u1.y, a, b); acc.z += a; acc.w += b;
        bf2x_to_f32(u2.x, a, b); acc.x += a; acc.y += b;
        bf2x_to_f32(u2.y, a, b); acc.z += a; acc.w += b;
        bf2x_to_f32(u3.x, a, b); acc.x += a; acc.y += b;
        bf2x_to_f32(u3.y, a, b); acc.z += a; acc.w += b;
    }
    for (; t < cnt; ++t) {
        const int s = g_csr[off + t];
        const uint2 u = fb[(size_t)s * 32];
        float a, b;
        bf2x_to_f32(u.x, a, b); acc.x += a; acc.y += b;
        bf2x_to_f32(u.y, a, b); acc.z += a; acc.w += b;
    }
    const float r = g_rdeg[node];
    acc.x *= r; acc.y *= r; acc.z *= r; acc.w *= r;
    // lane covers elems [lane*4, lane*4+4)
    *reinterpret_cast<float4*>(g_hn + (size_t)node * D + lane * 4) = acc;
}

// ===========================================================================
// GEMM: out = [feat | g_hn] (M x 256) @ W-images + bias   (tf32 mma.sync)
// CTA 128x128, 8 warps of 64x32, K chunked at 64; smem stride 68.
// ===========================================================================
#define ASTRIDE 68

__global__ __launch_bounds__(256, 2) void gemm_kernel(
    const float* __restrict__ feat,
    float* __restrict__ out,
    int M) {
    extern __shared__ float smem[];
    float* As = smem;                      // [128][ASTRIDE]
    float* Bs = smem + 128 * ASTRIDE;      // [128][ASTRIDE]

    const int tid  = threadIdx.x;
    const int wid  = tid >> 5;
    const int lane = tid & 31;
    const int blockRow = blockIdx.x * 128;

    const int wm = wid >> 2;
    const int wn = wid & 3;
    const int qr = lane >> 2;
    const int qc = lane & 3;

    float acc[4][4][4];
#pragma unroll
    for (int mt = 0; mt < 4; ++mt)
#pragma unroll
        for (int nt = 0; nt < 4; ++nt)
#pragma unroll
            for (int j = 0; j < 4; ++j) acc[mt][nt][j] = 0.f;

#pragma unroll 1
    for (int it = 0; it < 4; ++it) {
        const int h     = it >> 1;
        const int cbase = (it & 1) * 64;
        const float* Ag = h ? g_hn : feat;

        if (it) __syncthreads();

#pragma unroll
        for (int j = 0; j < 8; ++j) {
            const int g   = j * 256 + tid;
            const int row = g >> 4;
            const int c4  = (g & 15) * 4;
            const int grow = blockRow + row;
            float4 v = make_float4(0.f, 0.f, 0.f, 0.f);
            if (grow < M)
                v = *reinterpret_cast<const float4*>(
                    Ag + (size_t)grow * D + cbase + c4);
            float* dstp = As + row * ASTRIDE + c4;
            dstp[0] = __uint_as_float(to_tf32(v.x));
            dstp[1] = __uint_as_float(to_tf32(v.y));
            dstp[2] = __uint_as_float(to_tf32(v.z));
            dstp[3] = __uint_as_float(to_tf32(v.w));
        }
#pragma unroll
        for (int j = 0; j < 8; ++j) {
            const int g   = j * 256 + tid;
            const int row = g >> 4;
            const int c4  = (g & 15) * 4;
            const float4 v = *reinterpret_cast<const float4*>(
                g_W[h] + (size_t)row * 256 + cbase + c4);
            *reinterpret_cast<float4*>(Bs + row * ASTRIDE + c4) = v;
        }
        __syncthreads();

#pragma unroll
        for (int ks = 0; ks < 8; ++ks) {
            const int kb = ks * 8;
            uint32_t a[4][4], b[4][2];
#pragma unroll
            for (int mt = 0; mt < 4; ++mt) {
                const int rb = wm * 64 + mt * 16;
                const uint32_t* ap =
                    reinterpret_cast<const uint32_t*>(As + (rb + qr) * ASTRIDE + kb + qc);
                a[mt][0] = ap[0];
                a[mt][2] = ap[4];
                const uint32_t* ap8 =
                    reinterpret_cast<const uint32_t*>(As + (rb + qr + 8) * ASTRIDE + kb + qc);
                a[mt][1] = ap8[0];
                a[mt][3] = ap8[4];
            }
#pragma unroll
            for (int nt = 0; nt < 4; ++nt) {
                const int nb = wn * 32 + nt * 8;
                const uint32_t* bp =
                    reinterpret_cast<const uint32_t*>(Bs + (nb + qr) * ASTRIDE + kb + qc);
                b[nt][0] = bp[0];
                b[nt][1] = bp[4];
            }
#pragma unroll
            for (int mt = 0; mt < 4; ++mt)
#pragma unroll
                for (int nt = 0; nt < 4; ++nt)
                    mma_tf32(acc[mt][nt][0], acc[mt][nt][1],
                             acc[mt][nt][2], acc[mt][nt][3],
                             a[mt][0], a[mt][1], a[mt][2], a[mt][3],
                             b[nt][0], b[nt][1]);
        }
    }

#pragma unroll
    for (int mt = 0; mt < 4; ++mt) {
        const int r0 = blockRow + wm * 64 + mt * 16 + qr;
#pragma unroll
        for (int nt = 0; nt < 4; ++nt) {
            const int col = wn * 32 + nt * 8 + qc * 2;
            const float b0 = g_bias[col];
            const float b1 = g_bias[col + 1];
            if (r0 < M) {
                float2 o = make_float2(acc[mt][nt][0] + b0, acc[mt][nt][1] + b1);
                *reinterpret_cast<float2*>(out + (size_t)r0 * D + col) = o;
            }
            if (r0 + 8 < M) {
                float2 o = make_float2(acc[mt][nt][2] + b0, acc[mt][nt][3] + b1);
                *reinterpret_cast<float2*>(out + (size_t)(r0 + 8) * D + col) = o;
            }
        }
    }
}

// ---------------------------------------------------------------------------
extern "C" void kernel_launch(void* const* d_in, const int* in_sizes, int n_in,
                              void* d_out, int out_size) {
    const float* feat   = (const float*)d_in[0];
    const int*   src    = (const int*)d_in[1];
    const int*   dst    = (const int*)d_in[2];
    const float* Wself  = (const float*)d_in[3];
    const float* bself  = (const float*)d_in[4];
    const float* Wneigh = (const float*)d_in[5];
    const float* bneigh = (const float*)d_in[6];
    float*       out    = (float*)d_out;

    const int E = in_sizes[1];
    const int M = in_sizes[0] / D;
    const int nScanBlocks = (N_NODES + 1023) / 1024;   // 98
    const int GEMM_SMEM = 2 * 128 * ASTRIDE * 4;       // 69632 B

    cudaFuncSetAttribute(gemm_kernel, cudaFuncAttributeMaxDynamicSharedMemorySize,
                         GEMM_SMEM);

    prep_kernel<<<(N_NODES + 255) / 256, 256>>>(Wself, Wneigh, bself, bneigh);
    feat2bf16_kernel<<<1024, 256>>>(feat);
    hist_kernel<<<148 * 16, 256>>>(dst, E);
    scan_block_kernel<<<nScanBlocks, 1024>>>();
    scan_sums_kernel<<<1, 128>>>(nScanBlocks);
    scan_fixup_kernel<<<(N_NODES + 255) / 256, 256>>>();
    scatter_kernel<<<148 * 16, 256>>>(src, dst, E);
    agg_kernel<<<(N_NODES * 32 + 255) / 256, 256>>>();
    gemm_kernel<<<(M + 127) / 128, 256, GEMM_SMEM>>>(feat, out, M);
}

// round 8
// speedup vs baseline: 2.5970x; 1.0186x over previous
#include <cuda_runtime.h>
#include <cuda_bf16.h>
#include <cuda_fp16.h>
#include <cstdint>
#include <cstddef>

#define N_NODES 100000
#define D 128
#define E_CAP 3400000
#define SCAN_BLOCKS 98   // ceil(N_NODES / 1024)

// ---- device scratch (allocation-free rule: __device__ globals) ----
__device__ __align__(16) __half g_hnh[(size_t)N_NODES * D];           // 25.6 MB
__device__ __align__(16) __nv_bfloat16 g_featb[(size_t)N_NODES * D];  // 25.6 MB
__device__ __align__(16) int      g_count[N_NODES];
__device__ __align__(16) int      g_off[N_NODES];
__device__ __align__(16) int      g_cursor[N_NODES];
__device__ __align__(16) float    g_rdeg[N_NODES];
__device__ __align__(16) int      g_csr[E_CAP];
__device__ __align__(16) unsigned g_state[128];       // lookback: aggregate+1, 0=empty
// W transposed to [half][n][k-image], tf32-rounded fp32 bits
__device__ __align__(16) float g_W[2][128 * 256];
__device__ __align__(16) float g_bias[D];

// ===========================================================================
// helpers
// ===========================================================================
__device__ __forceinline__ uint32_t to_tf32(float f) {
    uint32_t r;
    asm("cvt.rna.tf32.f32 %0, %1;" : "=r"(r) : "f"(f));
    return r;
}

__device__ __forceinline__ void mma_tf32(float& c0, float& c1, float& c2, float& c3,
                                         uint32_t a0, uint32_t a1, uint32_t a2, uint32_t a3,
                                         uint32_t b0, uint32_t b1) {
    asm volatile(
        "mma.sync.aligned.m16n8k8.row.col.f32.tf32.tf32.f32 "
        "{%0,%1,%2,%3}, {%4,%5,%6,%7}, {%8,%9}, {%0,%1,%2,%3};"
        : "+f"(c0), "+f"(c1), "+f"(c2), "+f"(c3)
        : "r"(a0), "r"(a1), "r"(a2), "r"(a3), "r"(b0), "r"(b1));
}

__device__ __forceinline__ void bf2x_to_f32(uint32_t u, float& lo, float& hi) {
    lo = __uint_as_float(u << 16);
    hi = __uint_as_float(u & 0xFFFF0000u);
}

__device__ __forceinline__ uint32_t h2_bits(__half2 h) {
    __half2_raw r = *reinterpret_cast<__half2_raw*>(&h);
    return (uint32_t)r.x | ((uint32_t)r.y << 16);
}
__device__ __forceinline__ __half2 bits_h2(uint32_t u) {
    __half2_raw r;
    r.x = (unsigned short)(u & 0xFFFF);
    r.y = (unsigned short)(u >> 16);
    return *reinterpret_cast<__half2*>(&r);
}

// ===========================================================================
// prep (one launch): W transpose+tf32, fused bias, zero counters & lookback
// state, feat fp32 -> bf16 image. Grid-stride everything.
// ===========================================================================
__global__ void prep_kernel(const float* __restrict__ feat,
                            const float* __restrict__ Wself,
                            const float* __restrict__ Wneigh,
                            const float* __restrict__ bself,
                            const float* __restrict__ bneigh) {
    const int gsz = gridDim.x * blockDim.x;
    const int gtid = blockIdx.x * blockDim.x + threadIdx.x;

    if (gtid < 128) {
        g_bias[gtid] = bself[gtid] + bneigh[gtid];
        g_state[gtid] = 0u;
    }
    for (int i = gtid; i < N_NODES; i += gsz) g_count[i] = 0;
    for (int i = gtid; i < 2 * 128 * 128; i += gsz) {
        const int h = i >> 14;
        const int n = (i >> 7) & 127;
        const int k = i & 127;
        const float* W = h ? Wneigh : Wself;
        g_W[h][n * 256 + k] = __uint_as_float(to_tf32(W[k * 128 + n]));
    }
    const size_t n4 = (size_t)N_NODES * D / 4;
    for (size_t j = gtid; j < n4; j += gsz) {
        float4 v = reinterpret_cast<const float4*>(feat)[j];
        uint32_t p0 = ((uint32_t)__bfloat16_as_ushort(__float2bfloat16(v.y)) << 16)
                    | (uint32_t)__bfloat16_as_ushort(__float2bfloat16(v.x));
        uint32_t p1 = ((uint32_t)__bfloat16_as_ushort(__float2bfloat16(v.w)) << 16)
                    | (uint32_t)__bfloat16_as_ushort(__float2bfloat16(v.z));
        reinterpret_cast<uint2*>(g_featb)[j] = make_uint2(p0, p1);
    }
}

// ===========================================================================
// histogram
// ===========================================================================
__global__ void hist_kernel(const int* __restrict__ dst, int E) {
    int i = blockIdx.x * blockDim.x + threadIdx.x;
    int stride = gridDim.x * blockDim.x;
    for (int e = i; e < E; e += stride) atomicAdd(&g_count[dst[e]], 1);
}

// ===========================================================================
// single-pass scan with decoupled lookback (98 blocks, all co-resident).
// Also initializes cursor and rdeg.
// ===========================================================================
__global__ __launch_bounds__(1024) void scan_kernel() {
    __shared__ int wsum[32];
    __shared__ int s_prefix;

    const int tid  = threadIdx.x;
    const int lane = tid & 31;
    const int wid  = tid >> 5;
    const int b    = blockIdx.x;
    const int gid  = b * 1024 + tid;

    const int v = (gid < N_NODES) ? g_count[gid] : 0;

    // warp inclusive scan
    int x = v;
#pragma unroll
    for (int o = 1; o < 32; o <<= 1) {
        int y = __shfl_up_sync(0xFFFFFFFFu, x, o);
        if (lane >= o) x += y;
    }
    if (lane == 31) wsum[wid] = x;
    __syncthreads();
    if (wid == 0) {
        int s = wsum[lane];
#pragma unroll
        for (int o = 1; o < 32; o <<= 1) {
            int y = __shfl_up_sync(0xFFFFFFFFu, s, o);
            if (lane >= o) s += y;
        }
        wsum[lane] = s;
    }
    __syncthreads();
    const int incl = x + (wid ? wsum[wid - 1] : 0);
    const int block_total = wsum[31];

    // publish own aggregate (sentinel +1), then warp 0 sums all predecessors
    if (tid == 0) atomicExch(&g_state[b], (unsigned)(block_total + 1));
    if (wid == 0) {
        int run = 0;
        for (int base = 0; base < b; base += 32) {
            const int p = base + lane;
            unsigned u = 0;
            if (p < b) {
                do { u = atomicAdd(&g_state[p], 0u); } while (u == 0);
                run += (int)(u - 1);
            }
        }
        __syncwarp();
#pragma unroll
        for (int o = 16; o > 0; o >>= 1) run += __shfl_down_sync(0xFFFFFFFFu, run, o);
        if (lane == 0) s_prefix = run;
    }
    __syncthreads();

    if (gid < N_NODES) {
        const int excl = s_prefix + incl - v;
        g_off[gid]    = excl;
        g_cursor[gid] = excl;
        g_rdeg[gid]   = 1.0f / fmaxf((float)v, 1.0f);
    }
}

// ===========================================================================
// scatter: bucket src ids by dst
// ===========================================================================
__global__ void scatter_kernel(const int* __restrict__ src,
                               const int* __restrict__ dst, int E) {
    int i = blockIdx.x * blockDim.x + threadIdx.x;
    int stride = gridDim.x * blockDim.x;
    for (int e = i; e < E; e += stride) {
        int pos = atomicAdd(&g_cursor[dst[e]], 1);
        g_csr[pos] = src[e];
    }
}

// ===========================================================================
// aggregate: one warp per node, bf16 gathers, fp32 accumulate, fp16 store
// ===========================================================================
__global__ __launch_bounds__(256) void agg_kernel() {
    const int lane = threadIdx.x & 31;
    const int node = (blockIdx.x * blockDim.x + threadIdx.x) >> 5;
    if (node >= N_NODES) return;

    const int off = g_off[node];
    const int cnt = g_count[node];
    const uint2* fb = reinterpret_cast<const uint2*>(g_featb) + lane;

    float4 acc = make_float4(0.f, 0.f, 0.f, 0.f);
    int t = 0;
    for (; t + 4 <= cnt; t += 4) {
        const int s0 = g_csr[off + t + 0];
        const int s1 = g_csr[off + t + 1];
        const int s2 = g_csr[off + t + 2];
        const int s3 = g_csr[off + t + 3];
        const uint2 u0 = fb[(size_t)s0 * 32];
        const uint2 u1 = fb[(size_t)s1 * 32];
        const uint2 u2 = fb[(size_t)s2 * 32];
        const uint2 u3 = fb[(size_t)s3 * 32];
        float a, b;
        bf2x_to_f32(u0.x, a, b); acc.x += a; acc.y += b;
        bf2x_to_f32(u0.y, a, b); acc.z += a; acc.w += b;
        bf2x_to_f32(u1.x, a, b); acc.x += a; acc.y += b;
        bf2x_to_f32(u1.y, a, b); acc.z += a; acc.w += b;
        bf2x_to_f32(u2.x, a, b); acc.x += a; acc.y += b;
        bf2x_to_f32(u2.y, a, b); acc.z += a; acc.w += b;
        bf2x_to_f32(u3.x, a, b); acc.x += a; acc.y += b;
        bf2x_to_f32(u3.y, a, b); acc.z += a; acc.w += b;
    }
    for (; t < cnt; ++t) {
        const int s = g_csr[off + t];
        const uint2 u = fb[(size_t)s * 32];
        float a, b;
        bf2x_to_f32(u.x, a, b); acc.x += a; acc.y += b;
        bf2x_to_f32(u.y, a, b); acc.z += a; acc.w += b;
    }
    const float r = g_rdeg[node];
    const __half2 p0 = __floats2half2_rn(acc.x * r, acc.y * r);
    const __half2 p1 = __floats2half2_rn(acc.z * r, acc.w * r);
    *reinterpret_cast<uint2*>(g_hnh + (size_t)node * D + lane * 4) =
        make_uint2(h2_bits(p0), h2_bits(p1));
}

// ===========================================================================
// GEMM: out = [feat | g_hnh] (M x 256) @ W-images + bias   (tf32 mma.sync)
// CTA 128x128, 8 warps of 64x32, K chunked at 64; smem stride 68.
// ===========================================================================
#define ASTRIDE 68

__global__ __launch_bounds__(256, 2) void gemm_kernel(
    const float* __restrict__ feat,
    float* __restrict__ out,
    int M) {
    extern __shared__ float smem[];
    float* As = smem;                      // [128][ASTRIDE]
    float* Bs = smem + 128 * ASTRIDE;      // [128][ASTRIDE]

    const int tid  = threadIdx.x;
    const int wid  = tid >> 5;
    const int lane = tid & 31;
    const int blockRow = blockIdx.x * 128;

    const int wm = wid >> 2;
    const int wn = wid & 3;
    const int qr = lane >> 2;
    const int qc = lane & 3;

    float acc[4][4][4];
#pragma unroll
    for (int mt = 0; mt < 4; ++mt)
#pragma unroll
        for (int nt = 0; nt < 4; ++nt)
#pragma unroll
            for (int j = 0; j < 4; ++j) acc[mt][nt][j] = 0.f;

#pragma unroll 1
    for (int it = 0; it < 4; ++it) {
        const int h     = it >> 1;
        const int cbase = (it & 1) * 64;

        if (it) __syncthreads();

        // ---- A tile: 128x64 -> tf32-rounded smem ----
#pragma unroll
        for (int j = 0; j < 8; ++j) {
            const int g   = j * 256 + tid;
            const int row = g >> 4;
            const int c4  = (g & 15) * 4;
            const int grow = blockRow + row;
            float4 v = make_float4(0.f, 0.f, 0.f, 0.f);
            if (grow < M) {
                if (h == 0) {
                    v = *reinterpret_cast<const float4*>(
                        feat + (size_t)grow * D + cbase + c4);
                } else {
                    const uint2 u = *reinterpret_cast<const uint2*>(
                        g_hnh + (size_t)grow * D + cbase + c4);
                    const __half2 h0 = bits_h2(u.x);
                    const __half2 h1 = bits_h2(u.y);
                    v.x = __low2float(h0);  v.y = __high2float(h0);
                    v.z = __low2float(h1);  v.w = __high2float(h1);
                }
            }
            float* dstp = As + row * ASTRIDE + c4;
            dstp[0] = __uint_as_float(to_tf32(v.x));
            dstp[1] = __uint_as_float(to_tf32(v.y));
            dstp[2] = __uint_as_float(to_tf32(v.z));
            dstp[3] = __uint_as_float(to_tf32(v.w));
        }
        // ---- B tile: copy pre-rounded [n][k-chunk] ----
#pragma unroll
        for (int j = 0; j < 8; ++j) {
            const int g   = j * 256 + tid;
            const int row = g >> 4;
            const int c4  = (g & 15) * 4;
            const float4 v = *reinterpret_cast<const float4*>(
                g_W[h] + (size_t)row * 256 + cbase + c4);
            *reinterpret_cast<float4*>(Bs + row * ASTRIDE + c4) = v;
        }
        __syncthreads();

#pragma unroll
        for (int ks = 0; ks < 8; ++ks) {
            const int kb = ks * 8;
            uint32_t a[4][4], b[4][2];
#pragma unroll
            for (int mt = 0; mt < 4; ++mt) {
                const int rb = wm * 64 + mt * 16;
                const uint32_t* ap =
                    reinterpret_cast<const uint32_t*>(As + (rb + qr) * ASTRIDE + kb + qc);
                a[mt][0] = ap[0];
                a[mt][2] = ap[4];
                const uint32_t* ap8 =
                    reinterpret_cast<const uint32_t*>(As + (rb + qr + 8) * ASTRIDE + kb + qc);
                a[mt][1] = ap8[0];
                a[mt][3] = ap8[4];
            }
#pragma unroll
            for (int nt = 0; nt < 4; ++nt) {
                const int nb = wn * 32 + nt * 8;
                const uint32_t* bp =
                    reinterpret_cast<const uint32_t*>(Bs + (nb + qr) * ASTRIDE + kb + qc);
                b[nt][0] = bp[0];
                b[nt][1] = bp[4];
            }
#pragma unroll
            for (int mt = 0; mt < 4; ++mt)
#pragma unroll
                for (int nt = 0; nt < 4; ++nt)
                    mma_tf32(acc[mt][nt][0], acc[mt][nt][1],
                             acc[mt][nt][2], acc[mt][nt][3],
                             a[mt][0], a[mt][1], a[mt][2], a[mt][3],
                             b[nt][0], b[nt][1]);
        }
    }

#pragma unroll
    for (int mt = 0; mt < 4; ++mt) {
        const int r0 = blockRow + wm * 64 + mt * 16 + qr;
#pragma unroll
        for (int nt = 0; nt < 4; ++nt) {
            const int col = wn * 32 + nt * 8 + qc * 2;
            const float b0 = g_bias[col];
            const float b1 = g_bias[col + 1];
            if (r0 < M) {
                float2 o = make_float2(acc[mt][nt][0] + b0, acc[mt][nt][1] + b1);
                *reinterpret_cast<float2*>(out + (size_t)r0 * D + col) = o;
            }
            if (r0 + 8 < M) {
                float2 o = make_float2(acc[mt][nt][2] + b0, acc[mt][nt][3] + b1);
                *reinterpret_cast<float2*>(out + (size_t)(r0 + 8) * D + col) = o;
            }
        }
    }
}

// ---------------------------------------------------------------------------
extern "C" void kernel_launch(void* const* d_in, const int* in_sizes, int n_in,
                              void* d_out, int out_size) {
    const float* feat   = (const float*)d_in[0];
    const int*   src    = (const int*)d_in[1];
    const int*   dst    = (const int*)d_in[2];
    const float* Wself  = (const float*)d_in[3];
    const float* bself  = (const float*)d_in[4];
    const float* Wneigh = (const float*)d_in[5];
    const float* bneigh = (const float*)d_in[6];
    float*       out    = (float*)d_out;

    const int E = in_sizes[1];
    const int M = in_sizes[0] / D;
    const int GEMM_SMEM = 2 * 128 * ASTRIDE * 4;       // 69632 B

    cudaFuncSetAttribute(gemm_kernel, cudaFuncAttributeMaxDynamicSharedMemorySize,
                         GEMM_SMEM);

    prep_kernel<<<1024, 256>>>(feat, Wself, Wneigh, bself, bneigh);
    hist_kernel<<<148 * 16, 256>>>(dst, E);
    scan_kernel<<<SCAN_BLOCKS, 1024>>>();
    scatter_kernel<<<148 * 16, 256>>>(src, dst, E);
    agg_kernel<<<(N_NODES * 32 + 255) / 256, 256>>>();
    gemm_kernel<<<(M + 127) / 128, 256, GEMM_SMEM>>>(feat, out, M);
}